// round 15
// baseline (speedup 1.0000x reference)
#include <cuda_runtime.h>
#include <cuda_bf16.h>
#include <cstdint>

#define Ddim 128
#define Tdim 1024
#define Bdim 128
#define CH3 (3 * Ddim)
#define NCHUNK 16
#define TCHUNK (Tdim / NCHUNK)
#define ROWS_PB 64
#define NWARPS 8

// ---------------------------------------------------------------------------
// Device globals
// ---------------------------------------------------------------------------
__device__ float g_partial[Bdim * NCHUNK * Ddim];
// Packed E = (K - I) bf16 fragments: [n(16)][k(8)][lane(32)] -> {b0, b1}
__device__ uint2 g_Epk[16 * 8 * 32];

// SMEM layout (per CTA)
#define SM_B     0                                  // 32768 B (E frags)
#define SM_A     32768
#define A_STRIDE 272
#define TILE_A   (16 * A_STRIDE)                    // 4352 B per warp-pair
#define SM_MEANS (SM_A + 4 * TILE_A)                // 50176
#define SM_TOTAL (SM_MEANS + 512)                   // 50688 -> 4 CTAs/SM

// ---------------------------------------------------------------------------
__device__ __forceinline__ uint32_t smem_u32(const void* p) {
    uint32_t a;
    asm("{ .reg .u64 t; cvta.to.shared.u64 t, %1; cvt.u32.u64 %0, t; }" : "=r"(a) : "l"(p));
    return a;
}

__device__ __forceinline__ void mma16816(float* d, const uint32_t* a,
                                         uint32_t b0, uint32_t b1) {
    asm volatile(
        "mma.sync.aligned.m16n8k16.row.col.f32.bf16.bf16.f32 "
        "{%0,%1,%2,%3}, {%4,%5,%6,%7}, {%8,%9}, {%0,%1,%2,%3};"
        : "+f"(d[0]), "+f"(d[1]), "+f"(d[2]), "+f"(d[3])
        : "r"(a[0]), "r"(a[1]), "r"(a[2]), "r"(a[3]), "r"(b0), "r"(b1));
}

__device__ __forceinline__ void ldmatrix4(uint32_t* r, uint32_t addr) {
    asm volatile("ldmatrix.sync.aligned.m8n8.x4.shared.b16 {%0,%1,%2,%3}, [%4];"
                 : "=r"(r[0]), "=r"(r[1]), "=r"(r[2]), "=r"(r[3]) : "r"(addr));
}

__device__ __forceinline__ float bf16lo_f(uint32_t u) {
    return __bfloat162float(*(__nv_bfloat16*)&u);
}
__device__ __forceinline__ float bf16hi_f(uint32_t u) {
    uint32_t h = u >> 16;
    return __bfloat162float(*(__nv_bfloat16*)&h);
}

// ---------------------------------------------------------------------------
// Pass 1: mean partials (float4 lanes, warp-per-row-group) + E fragment pack.
// ---------------------------------------------------------------------------
__global__ void prep_kernel(const float* __restrict__ x, const float* __restrict__ kmat) {
    if (blockIdx.y == NCHUNK) {
        if (blockIdx.x >= 32) return;
        const int e = blockIdx.x * 128 + threadIdx.x;
        const int n = e >> 8, k = (e >> 5) & 7, lane = e & 31;
        const int g = lane >> 2, tig = lane & 3;
        const int col = n * 8 + g;
        const int r0 = k * 16 + tig * 2;
        const float f00 = kmat[(r0 + 0) * Ddim + col] - ((r0 + 0) == col ? 1.f : 0.f);
        const float f01 = kmat[(r0 + 1) * Ddim + col] - ((r0 + 1) == col ? 1.f : 0.f);
        const float f10 = kmat[(r0 + 8) * Ddim + col] - ((r0 + 8) == col ? 1.f : 0.f);
        const float f11 = kmat[(r0 + 9) * Ddim + col] - ((r0 + 9) == col ? 1.f : 0.f);
        __nv_bfloat162 b0 = __floats2bfloat162_rn(f00, f01);
        __nv_bfloat162 b1 = __floats2bfloat162_rn(f10, f11);
        uint2 v;
        v.x = *(uint32_t*)&b0;
        v.y = *(uint32_t*)&b1;
        g_Epk[e] = v;
        return;
    }
    __shared__ float4 wsum[4][32];
    const int b = blockIdx.x;
    const int c = blockIdx.y;
    const int w = threadIdx.x >> 5;
    const int lane = threadIdx.x & 31;

    // warp w sums rows {w, w+4, ..., w+60} of this chunk; lane owns cols 4l..4l+3
    const float* p = x + ((size_t)b * Tdim + (size_t)c * TCHUNK + w) * CH3 + 4 * lane;
    float4 s0 = {0.f, 0.f, 0.f, 0.f}, s1 = {0.f, 0.f, 0.f, 0.f};
    float4 s2 = {0.f, 0.f, 0.f, 0.f}, s3 = {0.f, 0.f, 0.f, 0.f};
#pragma unroll 1
    for (int t = 0; t < TCHUNK; t += 16) {
        const float4 a0 = *(const float4*)(p + (size_t)(t + 0) * CH3);
        const float4 a1 = *(const float4*)(p + (size_t)(t + 4) * CH3);
        const float4 a2 = *(const float4*)(p + (size_t)(t + 8) * CH3);
        const float4 a3 = *(const float4*)(p + (size_t)(t + 12) * CH3);
        s0.x += a0.x; s0.y += a0.y; s0.z += a0.z; s0.w += a0.w;
        s1.x += a1.x; s1.y += a1.y; s1.z += a1.z; s1.w += a1.w;
        s2.x += a2.x; s2.y += a2.y; s2.z += a2.z; s2.w += a2.w;
        s3.x += a3.x; s3.y += a3.y; s3.z += a3.z; s3.w += a3.w;
    }
    float4 s;
    s.x = (s0.x + s1.x) + (s2.x + s3.x);
    s.y = (s0.y + s1.y) + (s2.y + s3.y);
    s.z = (s0.z + s1.z) + (s2.z + s3.z);
    s.w = (s0.w + s1.w) + (s2.w + s3.w);
    wsum[w][lane] = s;
    __syncthreads();

    if (w == 0) {
        const float4 u0 = wsum[0][lane];
        const float4 u1 = wsum[1][lane];
        const float4 u2 = wsum[2][lane];
        const float4 u3 = wsum[3][lane];
        float4 r;
        r.x = (u0.x + u1.x) + (u2.x + u3.x);
        r.y = (u0.y + u1.y) + (u2.y + u3.y);
        r.z = (u0.z + u1.z) + (u2.z + u3.z);
        r.w = (u0.w + u1.w) + (u2.w + u3.w);
        *(float4*)(g_partial + (b * NCHUNK + c) * Ddim + 4 * lane) = r;
    }
}

// ---------------------------------------------------------------------------
// Pass 2: warp-pair tiles, 4 CTAs/SM. Each pair of warps shares a 16-row A
// tile; each warp builds 8 rows and computes its 8 N-fragments.
// ---------------------------------------------------------------------------
__global__ void __launch_bounds__(256, 4)
cci_main(const float* __restrict__ x, float* __restrict__ out) {
    extern __shared__ char sm[];
    const uint32_t sbase = smem_u32(sm);

    const int tid = threadIdx.x;
    const int w = tid >> 5;
    const int lane = tid & 31;
    const int g = lane >> 2;
    const int tig = lane & 3;
    const int pair = w >> 1;
    const int half = w & 1;
    const int row0 = blockIdx.x * ROWS_PB;
    const int b = row0 / Tdim;

    // Stage packed E fragments (raw 32KB copy).
    {
        const uint4* src = (const uint4*)g_Epk;
        uint4* dst = (uint4*)(sm + SM_B);
#pragma unroll
        for (int i = tid; i < 2048; i += 256) dst[i] = src[i];
    }

    // Finalize mean for this b.
    if (tid < Ddim) {
        float m = 0.f;
#pragma unroll
        for (int c = 0; c < NCHUNK; ++c) m += g_partial[(b * NCHUNK + c) * Ddim + tid];
        ((float*)(sm + SM_MEANS))[tid] = m * (1.0f / Tdim);
    }
    __syncthreads();   // the ONLY block-wide sync

    const float4 mn = *(const float4*)(sm + SM_MEANS + 16 * lane);

    // ---- prologue: 8 rows/warp (its half of the pair tile), batches of 4 ----
    char* aHi = sm + SM_A + pair * TILE_A;
#pragma unroll
    for (int i0 = 0; i0 < 8; i0 += 4) {
        float4 y[4], wv[4];
#pragma unroll
        for (int q = 0; q < 4; ++q) {
            const float* xr =
                x + (size_t)(row0 + pair * 16 + half * 8 + i0 + q) * CH3;
            y[q]  = *(const float4*)(xr + 4 * lane);
            wv[q] = *(const float4*)(xr + Ddim + 4 * lane);
        }
#pragma unroll
        for (int q = 0; q < 4; ++q) {
            const int ri = half * 8 + i0 + q;          // row within tile
            const int row = row0 + pair * 16 + ri;

            float4 inten;
            inten.x = __expf(wv[q].x);
            inten.y = __expf(wv[q].y);
            inten.z = __expf(wv[q].z);
            inten.w = __expf(wv[q].w);
            *(float4*)(out + (size_t)row * CH3 + Ddim + 4 * lane) = inten;

            float s = (inten.x + inten.y) + (inten.z + inten.w);
#pragma unroll
            for (int off = 16; off; off >>= 1) s += __shfl_xor_sync(0xffffffffu, s, off);
            const float rs = 1.0f / s;

            float4 v;
            v.x = inten.x * rs * (y[q].x - mn.x);
            v.y = inten.y * rs * (y[q].y - mn.y);
            v.z = inten.z * rs * (y[q].z - mn.z);
            v.w = inten.w * rs * (y[q].w - mn.w);

            __nv_bfloat162 h01 = __floats2bfloat162_rn(v.x, v.y);
            __nv_bfloat162 h23 = __floats2bfloat162_rn(v.z, v.w);
            uint2 ph;
            ph.x = *(uint32_t*)&h01;
            ph.y = *(uint32_t*)&h23;
            *(uint2*)(aHi + ri * A_STRIDE + 8 * lane) = ph;
        }
    }
    // pair barrier: both halves of the tile visible before ldmatrix
    asm volatile("bar.sync %0, 64;" :: "r"(1 + pair) : "memory");

    // ---- GEMM: acc = A_hi @ E (warp covers its 8 N-fragments) ----
    float acc[8][4];
#pragma unroll
    for (int n = 0; n < 8; ++n)
#pragma unroll
        for (int c = 0; c < 4; ++c) acc[n][c] = 0.f;

    const uint32_t aAddr =
        sbase + SM_A + pair * TILE_A + (lane & 15) * A_STRIDE + (lane >> 4) * 16;
    const uint32_t bBase = sbase + SM_B + lane * 8;

#pragma unroll
    for (int k = 0; k < 8; ++k) {
        uint32_t ah[4];
        ldmatrix4(ah, aAddr + k * 32);
#pragma unroll
        for (int n = 0; n < 8; ++n) {
            const int nn = half * 8 + n;
            uint2 bf;
            asm volatile("ld.shared.v2.b32 {%0,%1}, [%2];"
                         : "=r"(bf.x), "=r"(bf.y)
                         : "r"(bBase + (uint32_t)((nn * 8 + k) * 256)));
            mma16816(acc[n], ah, bf.x, bf.y);
        }
    }

    // ---- epilogue: smooth = v + acc + mean; y_trans = y_obs - smooth ----
    const int ra = row0 + pair * 16 + g;
    const int rb = ra + 8;
    const float* meansp = (const float*)(sm + SM_MEANS);
#pragma unroll
    for (int n = 0; n < 8; ++n) {
        const int col = (half * 8 + n) * 8 + tig * 2;
        const float2 m2 = *(const float2*)(meansp + col);

        const uint32_t ha = *(const uint32_t*)(aHi + g * A_STRIDE + col * 2);
        const uint32_t hb = *(const uint32_t*)(aHi + (g + 8) * A_STRIDE + col * 2);

        float2 sa, sb;
        sa.x = bf16lo_f(ha) + acc[n][0] + m2.x;
        sa.y = bf16hi_f(ha) + acc[n][1] + m2.y;
        sb.x = bf16lo_f(hb) + acc[n][2] + m2.x;
        sb.y = bf16hi_f(hb) + acc[n][3] + m2.y;
        *(float2*)(out + (size_t)ra * CH3 + col) = sa;
        *(float2*)(out + (size_t)rb * CH3 + col) = sb;

        const float2 ya = *(const float2*)(x + (size_t)ra * CH3 + 2 * Ddim + col);
        const float2 yb = *(const float2*)(x + (size_t)rb * CH3 + 2 * Ddim + col);
        float2 ta, tb;
        ta.x = ya.x - sa.x;
        ta.y = ya.y - sa.y;
        tb.x = yb.x - sb.x;
        tb.y = yb.y - sb.y;
        *(float2*)(out + (size_t)ra * CH3 + 2 * Ddim + col) = ta;
        *(float2*)(out + (size_t)rb * CH3 + 2 * Ddim + col) = tb;
    }
}

// ---------------------------------------------------------------------------
extern "C" void kernel_launch(void* const* d_in, const int* in_sizes, int n_in,
                              void* d_out, int out_size) {
    const float* x;
    const float* kmat;
    if (in_sizes[0] == Ddim * Ddim) {
        kmat = (const float*)d_in[0];
        x = (const float*)d_in[1];
    } else {
        x = (const float*)d_in[0];
        kmat = (const float*)d_in[1];
    }
    float* out = (float*)d_out;

    cudaFuncSetAttribute(cci_main, cudaFuncAttributeMaxDynamicSharedMemorySize, SM_TOTAL);

    prep_kernel<<<dim3(Bdim, NCHUNK + 1), Ddim>>>(x, kmat);
    cci_main<<<(Bdim * Tdim) / ROWS_PB, 256, SM_TOTAL>>>(x, out);
}

// round 16
// speedup vs baseline: 1.0152x; 1.0152x over previous
#include <cuda_runtime.h>
#include <cuda_bf16.h>
#include <cstdint>

#define Ddim 128
#define Tdim 1024
#define Bdim 128
#define CH3 (3 * Ddim)
#define NCHUNK 16
#define TCHUNK (Tdim / NCHUNK)
#define ROWS_PB 64
#define NWARPS 8

// ---------------------------------------------------------------------------
// Device globals
// ---------------------------------------------------------------------------
__device__ float g_partial[Bdim * NCHUNK * Ddim];
// Packed E = (K - I) bf16 fragments: [n(16)][k(8)][lane(32)] -> {b0, b1}
__device__ uint2 g_Epk[16 * 8 * 32];

// SMEM layout (per CTA)
#define SM_B     0                                  // 32768 B (E frags)
#define SM_A     32768
#define A_STRIDE 272
#define TILE_A   (16 * A_STRIDE)                    // 4352 B per warp-pair
#define SM_MEANS (SM_A + 4 * TILE_A)                // 50176
#define SM_TOTAL (SM_MEANS + 512)                   // 50688 -> 4 CTAs/SM

// ---------------------------------------------------------------------------
__device__ __forceinline__ uint32_t smem_u32(const void* p) {
    uint32_t a;
    asm("{ .reg .u64 t; cvta.to.shared.u64 t, %1; cvt.u32.u64 %0, t; }" : "=r"(a) : "l"(p));
    return a;
}

__device__ __forceinline__ void mma16816(float* d, const uint32_t* a,
                                         uint32_t b0, uint32_t b1) {
    asm volatile(
        "mma.sync.aligned.m16n8k16.row.col.f32.bf16.bf16.f32 "
        "{%0,%1,%2,%3}, {%4,%5,%6,%7}, {%8,%9}, {%0,%1,%2,%3};"
        : "+f"(d[0]), "+f"(d[1]), "+f"(d[2]), "+f"(d[3])
        : "r"(a[0]), "r"(a[1]), "r"(a[2]), "r"(a[3]), "r"(b0), "r"(b1));
}

__device__ __forceinline__ void ldmatrix4(uint32_t* r, uint32_t addr) {
    asm volatile("ldmatrix.sync.aligned.m8n8.x4.shared.b16 {%0,%1,%2,%3}, [%4];"
                 : "=r"(r[0]), "=r"(r[1]), "=r"(r[2]), "=r"(r[3]) : "r"(addr));
}

__device__ __forceinline__ float bf16lo_f(uint32_t u) {
    return __bfloat162float(*(__nv_bfloat16*)&u);
}
__device__ __forceinline__ float bf16hi_f(uint32_t u) {
    uint32_t h = u >> 16;
    return __bfloat162float(*(__nv_bfloat16*)&h);
}

// ---------------------------------------------------------------------------
// Pass 1: mean partials (float4 lanes, warp-per-row-group) + E fragment pack.
// ---------------------------------------------------------------------------
__global__ void prep_kernel(const float* __restrict__ x, const float* __restrict__ kmat) {
    if (blockIdx.y == NCHUNK) {
        if (blockIdx.x >= 32) return;
        const int e = blockIdx.x * 128 + threadIdx.x;
        const int n = e >> 8, k = (e >> 5) & 7, lane = e & 31;
        const int g = lane >> 2, tig = lane & 3;
        const int col = n * 8 + g;
        const int r0 = k * 16 + tig * 2;
        const float f00 = kmat[(r0 + 0) * Ddim + col] - ((r0 + 0) == col ? 1.f : 0.f);
        const float f01 = kmat[(r0 + 1) * Ddim + col] - ((r0 + 1) == col ? 1.f : 0.f);
        const float f10 = kmat[(r0 + 8) * Ddim + col] - ((r0 + 8) == col ? 1.f : 0.f);
        const float f11 = kmat[(r0 + 9) * Ddim + col] - ((r0 + 9) == col ? 1.f : 0.f);
        __nv_bfloat162 b0 = __floats2bfloat162_rn(f00, f01);
        __nv_bfloat162 b1 = __floats2bfloat162_rn(f10, f11);
        uint2 v;
        v.x = *(uint32_t*)&b0;
        v.y = *(uint32_t*)&b1;
        g_Epk[e] = v;
        return;
    }
    __shared__ float4 wsum[4][32];
    const int b = blockIdx.x;
    const int c = blockIdx.y;
    const int w = threadIdx.x >> 5;
    const int lane = threadIdx.x & 31;

    // warp w sums rows {w, w+4, ..., w+60} of this chunk; lane owns cols 4l..4l+3
    const float* p = x + ((size_t)b * Tdim + (size_t)c * TCHUNK + w) * CH3 + 4 * lane;
    float4 s0 = {0.f, 0.f, 0.f, 0.f}, s1 = {0.f, 0.f, 0.f, 0.f};
    float4 s2 = {0.f, 0.f, 0.f, 0.f}, s3 = {0.f, 0.f, 0.f, 0.f};
#pragma unroll 1
    for (int t = 0; t < TCHUNK; t += 16) {
        const float4 a0 = *(const float4*)(p + (size_t)(t + 0) * CH3);
        const float4 a1 = *(const float4*)(p + (size_t)(t + 4) * CH3);
        const float4 a2 = *(const float4*)(p + (size_t)(t + 8) * CH3);
        const float4 a3 = *(const float4*)(p + (size_t)(t + 12) * CH3);
        s0.x += a0.x; s0.y += a0.y; s0.z += a0.z; s0.w += a0.w;
        s1.x += a1.x; s1.y += a1.y; s1.z += a1.z; s1.w += a1.w;
        s2.x += a2.x; s2.y += a2.y; s2.z += a2.z; s2.w += a2.w;
        s3.x += a3.x; s3.y += a3.y; s3.z += a3.z; s3.w += a3.w;
    }
    float4 s;
    s.x = (s0.x + s1.x) + (s2.x + s3.x);
    s.y = (s0.y + s1.y) + (s2.y + s3.y);
    s.z = (s0.z + s1.z) + (s2.z + s3.z);
    s.w = (s0.w + s1.w) + (s2.w + s3.w);
    wsum[w][lane] = s;
    __syncthreads();

    if (w == 0) {
        const float4 u0 = wsum[0][lane];
        const float4 u1 = wsum[1][lane];
        const float4 u2 = wsum[2][lane];
        const float4 u3 = wsum[3][lane];
        float4 r;
        r.x = (u0.x + u1.x) + (u2.x + u3.x);
        r.y = (u0.y + u1.y) + (u2.y + u3.y);
        r.z = (u0.z + u1.z) + (u2.z + u3.z);
        r.w = (u0.w + u1.w) + (u2.w + u3.w);
        *(float4*)(g_partial + (b * NCHUNK + c) * Ddim + 4 * lane) = r;
    }
}

// ---------------------------------------------------------------------------
// Pass 2: warp-pair tiles, 4 CTAs/SM. Each pair of warps shares a 16-row A
// tile; each warp builds 8 rows and computes its 8 N-fragments.
// ---------------------------------------------------------------------------
__global__ void __launch_bounds__(256, 4)
cci_main(const float* __restrict__ x, float* __restrict__ out) {
    extern __shared__ char sm[];
    const uint32_t sbase = smem_u32(sm);

    const int tid = threadIdx.x;
    const int w = tid >> 5;
    const int lane = tid & 31;
    const int g = lane >> 2;
    const int tig = lane & 3;
    const int pair = w >> 1;
    const int half = w & 1;
    const int row0 = blockIdx.x * ROWS_PB;
    const int b = row0 / Tdim;

    // Stage packed E fragments (raw 32KB copy).
    {
        const uint4* src = (const uint4*)g_Epk;
        uint4* dst = (uint4*)(sm + SM_B);
#pragma unroll
        for (int i = tid; i < 2048; i += 256) dst[i] = src[i];
    }

    // Finalize mean for this b.
    if (tid < Ddim) {
        float m = 0.f;
#pragma unroll
        for (int c = 0; c < NCHUNK; ++c) m += g_partial[(b * NCHUNK + c) * Ddim + tid];
        ((float*)(sm + SM_MEANS))[tid] = m * (1.0f / Tdim);
    }
    __syncthreads();   // the ONLY block-wide sync

    const float4 mn = *(const float4*)(sm + SM_MEANS + 16 * lane);

    // ---- prologue: 8 rows/warp (its half of the pair tile), batches of 4 ----
    char* aHi = sm + SM_A + pair * TILE_A;
#pragma unroll
    for (int i0 = 0; i0 < 8; i0 += 4) {
        float4 y[4], wv[4];
#pragma unroll
        for (int q = 0; q < 4; ++q) {
            const float* xr =
                x + (size_t)(row0 + pair * 16 + half * 8 + i0 + q) * CH3;
            y[q]  = *(const float4*)(xr + 4 * lane);
            wv[q] = *(const float4*)(xr + Ddim + 4 * lane);
        }
#pragma unroll
        for (int q = 0; q < 4; ++q) {
            const int ri = half * 8 + i0 + q;          // row within tile
            const int row = row0 + pair * 16 + ri;

            float4 inten;
            inten.x = __expf(wv[q].x);
            inten.y = __expf(wv[q].y);
            inten.z = __expf(wv[q].z);
            inten.w = __expf(wv[q].w);
            *(float4*)(out + (size_t)row * CH3 + Ddim + 4 * lane) = inten;

            float s = (inten.x + inten.y) + (inten.z + inten.w);
#pragma unroll
            for (int off = 16; off; off >>= 1) s += __shfl_xor_sync(0xffffffffu, s, off);
            const float rs = 1.0f / s;

            float4 v;
            v.x = inten.x * rs * (y[q].x - mn.x);
            v.y = inten.y * rs * (y[q].y - mn.y);
            v.z = inten.z * rs * (y[q].z - mn.z);
            v.w = inten.w * rs * (y[q].w - mn.w);

            __nv_bfloat162 h01 = __floats2bfloat162_rn(v.x, v.y);
            __nv_bfloat162 h23 = __floats2bfloat162_rn(v.z, v.w);
            uint2 ph;
            ph.x = *(uint32_t*)&h01;
            ph.y = *(uint32_t*)&h23;
            *(uint2*)(aHi + ri * A_STRIDE + 8 * lane) = ph;
        }
    }
    // pair barrier: both halves of the tile visible before ldmatrix
    asm volatile("bar.sync %0, 64;" :: "r"(1 + pair) : "memory");

    // ---- GEMM: acc = A_hi @ E (warp covers its 8 N-fragments) ----
    float acc[8][4];
#pragma unroll
    for (int n = 0; n < 8; ++n)
#pragma unroll
        for (int c = 0; c < 4; ++c) acc[n][c] = 0.f;

    const uint32_t aAddr =
        sbase + SM_A + pair * TILE_A + (lane & 15) * A_STRIDE + (lane >> 4) * 16;
    const uint32_t bBase = sbase + SM_B + lane * 8;

#pragma unroll
    for (int k = 0; k < 8; ++k) {
        uint32_t ah[4];
        ldmatrix4(ah, aAddr + k * 32);
#pragma unroll
        for (int n = 0; n < 8; ++n) {
            const int nn = half * 8 + n;
            uint2 bf;
            asm volatile("ld.shared.v2.b32 {%0,%1}, [%2];"
                         : "=r"(bf.x), "=r"(bf.y)
                         : "r"(bBase + (uint32_t)((nn * 8 + k) * 256)));
            mma16816(acc[n], ah, bf.x, bf.y);
        }
    }

    // ---- epilogue: smooth = v + acc + mean; y_trans = y_obs - smooth ----
    const int ra = row0 + pair * 16 + g;
    const int rb = ra + 8;
    const float* meansp = (const float*)(sm + SM_MEANS);
#pragma unroll
    for (int n = 0; n < 8; ++n) {
        const int col = (half * 8 + n) * 8 + tig * 2;
        const float2 m2 = *(const float2*)(meansp + col);

        const uint32_t ha = *(const uint32_t*)(aHi + g * A_STRIDE + col * 2);
        const uint32_t hb = *(const uint32_t*)(aHi + (g + 8) * A_STRIDE + col * 2);

        float2 sa, sb;
        sa.x = bf16lo_f(ha) + acc[n][0] + m2.x;
        sa.y = bf16hi_f(ha) + acc[n][1] + m2.y;
        sb.x = bf16lo_f(hb) + acc[n][2] + m2.x;
        sb.y = bf16hi_f(hb) + acc[n][3] + m2.y;
        *(float2*)(out + (size_t)ra * CH3 + col) = sa;
        *(float2*)(out + (size_t)rb * CH3 + col) = sb;

        const float2 ya = *(const float2*)(x + (size_t)ra * CH3 + 2 * Ddim + col);
        const float2 yb = *(const float2*)(x + (size_t)rb * CH3 + 2 * Ddim + col);
        float2 ta, tb;
        ta.x = ya.x - sa.x;
        ta.y = ya.y - sa.y;
        tb.x = yb.x - sb.x;
        tb.y = yb.y - sb.y;
        *(float2*)(out + (size_t)ra * CH3 + 2 * Ddim + col) = ta;
        *(float2*)(out + (size_t)rb * CH3 + 2 * Ddim + col) = tb;
    }
}

// ---------------------------------------------------------------------------
extern "C" void kernel_launch(void* const* d_in, const int* in_sizes, int n_in,
                              void* d_out, int out_size) {
    const float* x;
    const float* kmat;
    if (in_sizes[0] == Ddim * Ddim) {
        kmat = (const float*)d_in[0];
        x = (const float*)d_in[1];
    } else {
        x = (const float*)d_in[0];
        kmat = (const float*)d_in[1];
    }
    float* out = (float*)d_out;

    cudaFuncSetAttribute(cci_main, cudaFuncAttributeMaxDynamicSharedMemorySize, SM_TOTAL);

    prep_kernel<<<dim3(Bdim, NCHUNK + 1), Ddim>>>(x, kmat);
    cci_main<<<(Bdim * Tdim) / ROWS_PB, 256, SM_TOTAL>>>(x, out);
}

// round 17
// speedup vs baseline: 1.0165x; 1.0012x over previous
#include <cuda_runtime.h>
#include <cuda_bf16.h>
#include <cstdint>

#define Ddim 128
#define Tdim 1024
#define Bdim 128
#define CH3 (3 * Ddim)
#define NCHUNK 16
#define TCHUNK (Tdim / NCHUNK)
#define ROWS_PB 64
#define NWARPS 8

// ---------------------------------------------------------------------------
// Device globals
// ---------------------------------------------------------------------------
__device__ float g_partial[Bdim * NCHUNK * Ddim];
// Packed E = (K - I) bf16 fragments: [n(16)][k(8)][lane(32)] -> {b0, b1}
__device__ uint2 g_Epk[16 * 8 * 32];

// SMEM layout (per CTA)
#define SM_B     0                                  // 32768 B (E frags)
#define SM_A     32768
#define A_STRIDE 272
#define TILE_A   (16 * A_STRIDE)                    // 4352 B per warp-pair
#define SM_MEANS (SM_A + 4 * TILE_A)                // 50176
#define SM_TOTAL (SM_MEANS + 512)                   // 50688 -> 4 CTAs/SM

// ---------------------------------------------------------------------------
__device__ __forceinline__ uint32_t smem_u32(const void* p) {
    uint32_t a;
    asm("{ .reg .u64 t; cvta.to.shared.u64 t, %1; cvt.u32.u64 %0, t; }" : "=r"(a) : "l"(p));
    return a;
}

__device__ __forceinline__ void mma16816(float* d, const uint32_t* a,
                                         uint32_t b0, uint32_t b1) {
    asm volatile(
        "mma.sync.aligned.m16n8k16.row.col.f32.bf16.bf16.f32 "
        "{%0,%1,%2,%3}, {%4,%5,%6,%7}, {%8,%9}, {%0,%1,%2,%3};"
        : "+f"(d[0]), "+f"(d[1]), "+f"(d[2]), "+f"(d[3])
        : "r"(a[0]), "r"(a[1]), "r"(a[2]), "r"(a[3]), "r"(b0), "r"(b1));
}

__device__ __forceinline__ void ldmatrix4(uint32_t* r, uint32_t addr) {
    asm volatile("ldmatrix.sync.aligned.m8n8.x4.shared.b16 {%0,%1,%2,%3}, [%4];"
                 : "=r"(r[0]), "=r"(r[1]), "=r"(r[2]), "=r"(r[3]) : "r"(addr));
}

__device__ __forceinline__ float bf16lo_f(uint32_t u) {
    return __bfloat162float(*(__nv_bfloat16*)&u);
}
__device__ __forceinline__ float bf16hi_f(uint32_t u) {
    uint32_t h = u >> 16;
    return __bfloat162float(*(__nv_bfloat16*)&h);
}

// ---------------------------------------------------------------------------
// Pass 1: mean partials (float4 lanes, warp-per-row-group) + E fragment pack.
// ---------------------------------------------------------------------------
__global__ void prep_kernel(const float* __restrict__ x, const float* __restrict__ kmat) {
    if (blockIdx.y == NCHUNK) {
        if (blockIdx.x >= 32) return;
        const int e = blockIdx.x * 128 + threadIdx.x;
        const int n = e >> 8, k = (e >> 5) & 7, lane = e & 31;
        const int g = lane >> 2, tig = lane & 3;
        const int col = n * 8 + g;
        const int r0 = k * 16 + tig * 2;
        const float f00 = kmat[(r0 + 0) * Ddim + col] - ((r0 + 0) == col ? 1.f : 0.f);
        const float f01 = kmat[(r0 + 1) * Ddim + col] - ((r0 + 1) == col ? 1.f : 0.f);
        const float f10 = kmat[(r0 + 8) * Ddim + col] - ((r0 + 8) == col ? 1.f : 0.f);
        const float f11 = kmat[(r0 + 9) * Ddim + col] - ((r0 + 9) == col ? 1.f : 0.f);
        __nv_bfloat162 b0 = __floats2bfloat162_rn(f00, f01);
        __nv_bfloat162 b1 = __floats2bfloat162_rn(f10, f11);
        uint2 v;
        v.x = *(uint32_t*)&b0;
        v.y = *(uint32_t*)&b1;
        g_Epk[e] = v;
        return;
    }
    __shared__ float4 wsum[4][32];
    const int b = blockIdx.x;
    const int c = blockIdx.y;
    const int w = threadIdx.x >> 5;
    const int lane = threadIdx.x & 31;

    // warp w sums rows {w, w+4, ..., w+60} of this chunk; lane owns cols 4l..4l+3
    const float* p = x + ((size_t)b * Tdim + (size_t)c * TCHUNK + w) * CH3 + 4 * lane;
    float4 s0 = {0.f, 0.f, 0.f, 0.f}, s1 = {0.f, 0.f, 0.f, 0.f};
    float4 s2 = {0.f, 0.f, 0.f, 0.f}, s3 = {0.f, 0.f, 0.f, 0.f};
#pragma unroll 1
    for (int t = 0; t < TCHUNK; t += 16) {
        const float4 a0 = *(const float4*)(p + (size_t)(t + 0) * CH3);
        const float4 a1 = *(const float4*)(p + (size_t)(t + 4) * CH3);
        const float4 a2 = *(const float4*)(p + (size_t)(t + 8) * CH3);
        const float4 a3 = *(const float4*)(p + (size_t)(t + 12) * CH3);
        s0.x += a0.x; s0.y += a0.y; s0.z += a0.z; s0.w += a0.w;
        s1.x += a1.x; s1.y += a1.y; s1.z += a1.z; s1.w += a1.w;
        s2.x += a2.x; s2.y += a2.y; s2.z += a2.z; s2.w += a2.w;
        s3.x += a3.x; s3.y += a3.y; s3.z += a3.z; s3.w += a3.w;
    }
    float4 s;
    s.x = (s0.x + s1.x) + (s2.x + s3.x);
    s.y = (s0.y + s1.y) + (s2.y + s3.y);
    s.z = (s0.z + s1.z) + (s2.z + s3.z);
    s.w = (s0.w + s1.w) + (s2.w + s3.w);
    wsum[w][lane] = s;
    __syncthreads();

    if (w == 0) {
        const float4 u0 = wsum[0][lane];
        const float4 u1 = wsum[1][lane];
        const float4 u2 = wsum[2][lane];
        const float4 u3 = wsum[3][lane];
        float4 r;
        r.x = (u0.x + u1.x) + (u2.x + u3.x);
        r.y = (u0.y + u1.y) + (u2.y + u3.y);
        r.z = (u0.z + u1.z) + (u2.z + u3.z);
        r.w = (u0.w + u1.w) + (u2.w + u3.w);
        *(float4*)(g_partial + (b * NCHUNK + c) * Ddim + 4 * lane) = r;
    }
}

// ---------------------------------------------------------------------------
// Pass 2: warp-pair tiles, 4 CTAs/SM. Each pair of warps shares a 16-row A
// tile; each warp builds 8 rows and computes its 8 N-fragments.
// ---------------------------------------------------------------------------
__global__ void __launch_bounds__(256, 4)
cci_main(const float* __restrict__ x, float* __restrict__ out) {
    extern __shared__ char sm[];
    const uint32_t sbase = smem_u32(sm);

    const int tid = threadIdx.x;
    const int w = tid >> 5;
    const int lane = tid & 31;
    const int g = lane >> 2;
    const int tig = lane & 3;
    const int pair = w >> 1;
    const int half = w & 1;
    const int row0 = blockIdx.x * ROWS_PB;
    const int b = row0 / Tdim;

    // Stage packed E fragments (raw 32KB copy).
    {
        const uint4* src = (const uint4*)g_Epk;
        uint4* dst = (uint4*)(sm + SM_B);
#pragma unroll
        for (int i = tid; i < 2048; i += 256) dst[i] = src[i];
    }

    // Finalize mean for this b.
    if (tid < Ddim) {
        float m = 0.f;
#pragma unroll
        for (int c = 0; c < NCHUNK; ++c) m += g_partial[(b * NCHUNK + c) * Ddim + tid];
        ((float*)(sm + SM_MEANS))[tid] = m * (1.0f / Tdim);
    }
    __syncthreads();   // the ONLY block-wide sync

    const float4 mn = *(const float4*)(sm + SM_MEANS + 16 * lane);

    // ---- prologue: 8 rows/warp (its half of the pair tile), batches of 4 ----
    char* aHi = sm + SM_A + pair * TILE_A;
#pragma unroll
    for (int i0 = 0; i0 < 8; i0 += 4) {
        float4 y[4], wv[4];
#pragma unroll
        for (int q = 0; q < 4; ++q) {
            const float* xr =
                x + (size_t)(row0 + pair * 16 + half * 8 + i0 + q) * CH3;
            y[q]  = *(const float4*)(xr + 4 * lane);
            wv[q] = *(const float4*)(xr + Ddim + 4 * lane);
        }
#pragma unroll
        for (int q = 0; q < 4; ++q) {
            const int ri = half * 8 + i0 + q;          // row within tile
            const int row = row0 + pair * 16 + ri;

            float4 inten;
            inten.x = __expf(wv[q].x);
            inten.y = __expf(wv[q].y);
            inten.z = __expf(wv[q].z);
            inten.w = __expf(wv[q].w);
            *(float4*)(out + (size_t)row * CH3 + Ddim + 4 * lane) = inten;

            float s = (inten.x + inten.y) + (inten.z + inten.w);
#pragma unroll
            for (int off = 16; off; off >>= 1) s += __shfl_xor_sync(0xffffffffu, s, off);
            const float rs = 1.0f / s;

            float4 v;
            v.x = inten.x * rs * (y[q].x - mn.x);
            v.y = inten.y * rs * (y[q].y - mn.y);
            v.z = inten.z * rs * (y[q].z - mn.z);
            v.w = inten.w * rs * (y[q].w - mn.w);

            __nv_bfloat162 h01 = __floats2bfloat162_rn(v.x, v.y);
            __nv_bfloat162 h23 = __floats2bfloat162_rn(v.z, v.w);
            uint2 ph;
            ph.x = *(uint32_t*)&h01;
            ph.y = *(uint32_t*)&h23;
            *(uint2*)(aHi + ri * A_STRIDE + 8 * lane) = ph;
        }
    }
    // pair barrier: both halves of the tile visible before ldmatrix
    asm volatile("bar.sync %0, 64;" :: "r"(1 + pair) : "memory");

    // ---- GEMM: acc = A_hi @ E (warp covers its 8 N-fragments) ----
    float acc[8][4];
#pragma unroll
    for (int n = 0; n < 8; ++n)
#pragma unroll
        for (int c = 0; c < 4; ++c) acc[n][c] = 0.f;

    const uint32_t aAddr =
        sbase + SM_A + pair * TILE_A + (lane & 15) * A_STRIDE + (lane >> 4) * 16;
    const uint32_t bBase = sbase + SM_B + lane * 8;

#pragma unroll
    for (int k = 0; k < 8; ++k) {
        uint32_t ah[4];
        ldmatrix4(ah, aAddr + k * 32);
#pragma unroll
        for (int n = 0; n < 8; ++n) {
            const int nn = half * 8 + n;
            uint2 bf;
            asm volatile("ld.shared.v2.b32 {%0,%1}, [%2];"
                         : "=r"(bf.x), "=r"(bf.y)
                         : "r"(bBase + (uint32_t)((nn * 8 + k) * 256)));
            mma16816(acc[n], ah, bf.x, bf.y);
        }
    }

    // ---- epilogue: smooth = v + acc + mean; y_trans = y_obs - smooth ----
    const int ra = row0 + pair * 16 + g;
    const int rb = ra + 8;
    const float* meansp = (const float*)(sm + SM_MEANS);
#pragma unroll
    for (int n = 0; n < 8; ++n) {
        const int col = (half * 8 + n) * 8 + tig * 2;
        const float2 m2 = *(const float2*)(meansp + col);

        const uint32_t ha = *(const uint32_t*)(aHi + g * A_STRIDE + col * 2);
        const uint32_t hb = *(const uint32_t*)(aHi + (g + 8) * A_STRIDE + col * 2);

        float2 sa, sb;
        sa.x = bf16lo_f(ha) + acc[n][0] + m2.x;
        sa.y = bf16hi_f(ha) + acc[n][1] + m2.y;
        sb.x = bf16lo_f(hb) + acc[n][2] + m2.x;
        sb.y = bf16hi_f(hb) + acc[n][3] + m2.y;
        *(float2*)(out + (size_t)ra * CH3 + col) = sa;
        *(float2*)(out + (size_t)rb * CH3 + col) = sb;

        const float2 ya = *(const float2*)(x + (size_t)ra * CH3 + 2 * Ddim + col);
        const float2 yb = *(const float2*)(x + (size_t)rb * CH3 + 2 * Ddim + col);
        float2 ta, tb;
        ta.x = ya.x - sa.x;
        ta.y = ya.y - sa.y;
        tb.x = yb.x - sb.x;
        tb.y = yb.y - sb.y;
        *(float2*)(out + (size_t)ra * CH3 + 2 * Ddim + col) = ta;
        *(float2*)(out + (size_t)rb * CH3 + 2 * Ddim + col) = tb;
    }
}

// ---------------------------------------------------------------------------
extern "C" void kernel_launch(void* const* d_in, const int* in_sizes, int n_in,
                              void* d_out, int out_size) {
    const float* x;
    const float* kmat;
    if (in_sizes[0] == Ddim * Ddim) {
        kmat = (const float*)d_in[0];
        x = (const float*)d_in[1];
    } else {
        x = (const float*)d_in[0];
        kmat = (const float*)d_in[1];
    }
    float* out = (float*)d_out;

    cudaFuncSetAttribute(cci_main, cudaFuncAttributeMaxDynamicSharedMemorySize, SM_TOTAL);

    prep_kernel<<<dim3(Bdim, NCHUNK + 1), Ddim>>>(x, kmat);
    cci_main<<<(Bdim * Tdim) / ROWS_PB, 256, SM_TOTAL>>>(x, out);
}